// round 1
// baseline (speedup 1.0000x reference)
#include <cuda_runtime.h>
#include <math.h>

// ---------------------------------------------------------------------------
// BertAdapterCapsuleMask fused pipeline, fp32 baseline with f32x2 packed FMA.
// Shapes fixed: B=256 S=128 H=768 A=512 N=10 C=3 K=3, M = B*S = 32768.
// ---------------------------------------------------------------------------

#define MROWS 32768
#define HDIM  768
#define ADIM  512
#define NTASK 10
#define CCAP  3
#define KCAP  3

// Scratch (static device globals; no allocations anywhere)
__device__ float g_sem[(size_t)MROWS * 30];               //  3.9 MB  (c,n)-ordered per row
__device__ float g_vote[(size_t)KCAP * MROWS * CCAP];     //  1.2 MB  (K,M,C) row-major
__device__ float g_h2[(size_t)MROWS * HDIM];              // 100.7 MB
__device__ float g_a[(size_t)MROWS * ADIM];               //  67.1 MB
__device__ float g_gfc1[ADIM];
__device__ float g_gfc2[HDIM];
__device__ float g_glarger[HDIM];

// ---- packed fp32x2 helpers (Blackwell: scalar FFMA is half-rate; f32x2 is full-rate)
__device__ __forceinline__ unsigned long long pk2(float x) {
    unsigned long long r;
    asm("mov.b64 %0, {%1, %1};" : "=l"(r) : "f"(x));
    return r;
}
__device__ __forceinline__ void ffma2(unsigned long long& d, unsigned long long a,
                                      unsigned long long b) {
    asm("fma.rn.f32x2 %0, %1, %2, %0;" : "+l"(d) : "l"(a), "l"(b));
}
__device__ __forceinline__ void unpk2(unsigned long long v, float& lo, float& hi) {
    asm("mov.b64 {%0, %1}, %2;" : "=f"(lo), "=f"(hi) : "l"(v));
}

__device__ __forceinline__ float gelu_exact(float v) {
    return 0.5f * v * (1.0f + erff(v * 0.7071067811865476f));
}
__device__ __forceinline__ float sigmoid_(float z) {
    return 1.0f / (1.0f + expf(-z));
}

// ---------------------------------------------------------------------------
// K0: HAT gates.  g = sigmoid(s * e[t])
// ---------------------------------------------------------------------------
__global__ void k0_gates(const float* __restrict__ efc1, const float* __restrict__ efc2,
                         const float* __restrict__ elarger,
                         const int* __restrict__ tp, const int* __restrict__ sp) {
    int t = *tp;
    float s = (float)(*sp);
    int h = threadIdx.x;  // 768 threads
    g_glarger[h] = sigmoid_(s * elarger[t * HDIM + h]);
    g_gfc2[h]    = sigmoid_(s * efc2[t * HDIM + h]);
    if (h < ADIM) g_gfc1[h] = sigmoid_(s * efc1[t * ADIM + h]);
}

// ---------------------------------------------------------------------------
// K1: semantic-capsule skinny GEMM.
// g_sem[m][c*10+n] = dot(x[m,:], sem_w[n,:,c]) + sem_b[n,c]
// 128 rows/block, one row per thread; W-panel broadcast from smem; f32x2 acc.
// ---------------------------------------------------------------------------
__global__ __launch_bounds__(128) void k1_sem(const float* __restrict__ x,
                                              const float* __restrict__ semw,
                                              const float* __restrict__ semb) {
    __shared__ float Xs[128][65];   // pad 65 -> conflict-free column reads
    __shared__ float Ws[64][32];    // [kk][o], o = c*10+n, padded to 32 for 8B loads
    __shared__ float bs[32];

    int tid = threadIdx.x;
    int m0 = blockIdx.x * 128;

    if (tid < 30) {
        int c = tid / 10, n = tid % 10;
        bs[tid] = semb[n * 3 + c];
    }

    unsigned long long acc[15];
#pragma unroll
    for (int j = 0; j < 15; j++) acc[j] = 0ull;

    for (int k0 = 0; k0 < HDIM; k0 += 64) {
        // stage X tile 128x64 (coalesced float4 loads, scalar smem stores)
#pragma unroll
        for (int p = 0; p < 16; p++) {
            int e = p * 128 + tid;
            int r = e >> 4, c4 = e & 15;
            float4 v = *(const float4*)(x + (size_t)(m0 + r) * HDIM + k0 + c4 * 4);
            Xs[r][c4 * 4 + 0] = v.x;
            Xs[r][c4 * 4 + 1] = v.y;
            Xs[r][c4 * 4 + 2] = v.z;
            Xs[r][c4 * 4 + 3] = v.w;
        }
        // stage W panel 64x30 (gather from (N,H,C) layout; L2-hot, 92KB total)
#pragma unroll
        for (int p = 0; p < 15; p++) {
            int e = p * 128 + tid;
            int kk = e / 30, o = e % 30;
            int c = o / 10, n = o % 10;
            Ws[kk][o] = semw[n * HDIM * 3 + (k0 + kk) * 3 + c];
        }
        __syncthreads();

#pragma unroll 4
        for (int kk = 0; kk < 64; kk++) {
            unsigned long long x2 = pk2(Xs[tid][kk]);
#pragma unroll
            for (int j = 0; j < 15; j++) {
                unsigned long long w2 = *(const unsigned long long*)&Ws[kk][2 * j];
                ffma2(acc[j], x2, w2);
            }
        }
        __syncthreads();
    }

    int m = m0 + tid;
#pragma unroll
    for (int j = 0; j < 15; j++) {
        float lo, hi;
        unpk2(acc[j], lo, hi);
        g_sem[(size_t)m * 30 + 2 * j]     = lo + bs[2 * j];
        g_sem[(size_t)m * 30 + 2 * j + 1] = hi + bs[2 * j + 1];
    }
}

// ---------------------------------------------------------------------------
// K2: squash over tasks, build u (torch .view reinterpretation), priors,
//     3-iteration dynamic routing with tsv mask, write vote in (K,M,C) flat.
// One row per thread, all register-resident.
// ---------------------------------------------------------------------------
__global__ __launch_bounds__(256) void k2_route(const float* __restrict__ routew,
                                                const int* __restrict__ tp) {
    __shared__ float rw[KCAP * NTASK * CCAP * CCAP];  // 270
    int tid = threadIdx.x;
    if (tid < 270) rw[tid] = routew[tid];
    __syncthreads();

    int t = *tp;
    int m = blockIdx.x * 256 + tid;

    float v[30];
    const float* srow = &g_sem[(size_t)m * 30];
#pragma unroll
    for (int i = 0; i < 30; i++) v[i] = srow[i];

    // squash over n for each c  (axis=-1 of (B, S*C, N))
#pragma unroll
    for (int c = 0; c < 3; c++) {
        float sn = 1e-16f;
#pragma unroll
        for (int n = 0; n < 10; n++) { float q = v[c * 10 + n]; sn += q * q; }
        float sc = sqrtf(sn) / (1.0f + sn);
#pragma unroll
        for (int n = 0; n < 10; n++) v[c * 10 + n] *= sc;
    }

    // u[n][c] = flat30[n*3+c]  (row-major .view of the (c,n)-ordered block)
#pragma unroll
    for (int k = 0; k < 3; k++) {
        float pr[10][3];
#pragma unroll
        for (int n = 0; n < 10; n++) {
            float u0 = v[n * 3 + 0], u1 = v[n * 3 + 1], u2 = v[n * 3 + 2];
#pragma unroll
            for (int d = 0; d < 3; d++) {
                int b = ((k * 10 + n) * 3) * 3 + d;
                pr[n][d] = u0 * rw[b] + u1 * rw[b + 3] + u2 * rw[b + 6];
            }
        }
        float lg[10];
#pragma unroll
        for (int n = 0; n < 10; n++) lg[n] = 0.0f;

        float vote0 = 0.f, vote1 = 0.f, vote2 = 0.f;
#pragma unroll
        for (int it = 0; it < 3; it++) {
            float mx = -3.4e38f;
#pragma unroll
            for (int n = 0; n < 10; n++) {
                lg[n] = (n <= t) ? lg[n] : -10000.0f;  // logits*row + neg
                mx = fmaxf(mx, lg[n]);
            }
            float e[10], ssum = 0.f;
#pragma unroll
            for (int n = 0; n < 10; n++) { e[n] = expf(lg[n] - mx); ssum += e[n]; }
            float inv = 1.0f / ssum;
            vote0 = vote1 = vote2 = 0.f;
#pragma unroll
            for (int n = 0; n < 10; n++) {
                float p = e[n] * inv;
                vote0 += p * pr[n][0];
                vote1 += p * pr[n][1];
                vote2 += p * pr[n][2];
            }
            if (it < 2) {
                float sn = vote0 * vote0 + vote1 * vote1 + vote2 * vote2 + 1e-16f;
                float sc = sqrtf(sn) / (1.0f + sn);
                float o0 = vote0 * sc, o1 = vote1 * sc, o2 = vote2 * sc;
#pragma unroll
                for (int n = 0; n < 10; n++)
                    lg[n] += pr[n][0] * o0 + pr[n][1] * o1 + pr[n][2] * o2;
            }
        }
        size_t base = ((size_t)k * MROWS + m) * 3;
        g_vote[base + 0] = vote0;
        g_vote[base + 1] = vote1;
        g_vote[base + 2] = vote2;
    }
}

// ---------------------------------------------------------------------------
// K3: h2 = x + glarger * (vote9 @ larger_w + larger_b)
// vote9 read via the flat (K,M,C) -> (M,9) row-major reinterpretation.
// ---------------------------------------------------------------------------
__global__ __launch_bounds__(256) void k3_h2(const float* __restrict__ x,
                                             const float* __restrict__ lw,
                                             const float* __restrict__ lb) {
    __shared__ float v9[9];
    int m = blockIdx.x;
    int tid = threadIdx.x;
    if (tid < 9) v9[tid] = g_vote[(size_t)m * 9 + tid];
    __syncthreads();
#pragma unroll
    for (int p = 0; p < 3; p++) {
        int h = tid + p * 256;
        float acc = lb[h];
#pragma unroll
        for (int j = 0; j < 9; j++) acc += v9[j] * lw[j * HDIM + h];
        g_h2[(size_t)m * HDIM + h] = x[(size_t)m * HDIM + h] + g_glarger[h] * acc;
    }
}

// ---------------------------------------------------------------------------
// Adapter GEMMs: BM=128 BN=64 BK=32, 256 threads, per-thread 8x4 outputs,
// accumulators packed along M as f32x2 (full-rate fp32 on Blackwell).
// MODE 1: a   = gelu(h2 @ fc1_w + b) * gfc1
// MODE 2: out = x + gelu(a @ fc2_w + b) * gfc2
// ---------------------------------------------------------------------------
template <int KDIM, int NDIM, int MODE>
__global__ __launch_bounds__(256) void gemm_fused(const float* __restrict__ W,
                                                  const float* __restrict__ bias,
                                                  const float* __restrict__ xin,
                                                  float* __restrict__ outp) {
    __shared__ float As[32][132];  // [k][m], pad 132 (16B-aligned pair loads, mild conflicts)
    __shared__ float Bs[32][64];   // [k][n]

    const float* A    = (MODE == 1) ? g_h2 : g_a;
    const float* gate = (MODE == 1) ? g_gfc1 : g_gfc2;
    float* C          = (MODE == 1) ? g_a : outp;

    int tid = threadIdx.x;
    int tx = tid & 15, ty = tid >> 4;
    int n0 = blockIdx.x * 64;
    int m0 = blockIdx.y * 128;

    unsigned long long acc[4][4];
#pragma unroll
    for (int i = 0; i < 4; i++)
#pragma unroll
        for (int j = 0; j < 4; j++) acc[i][j] = 0ull;

    for (int k0 = 0; k0 < KDIM; k0 += 32) {
        // A tile 128x32, transposed into smem
#pragma unroll
        for (int p = 0; p < 4; p++) {
            int e = p * 256 + tid;
            int r = e >> 3, c4 = e & 7;
            float4 v = *(const float4*)(A + (size_t)(m0 + r) * KDIM + k0 + c4 * 4);
            As[c4 * 4 + 0][r] = v.x;
            As[c4 * 4 + 1][r] = v.y;
            As[c4 * 4 + 2][r] = v.z;
            As[c4 * 4 + 3][r] = v.w;
        }
        // B tile 32x64
#pragma unroll
        for (int p = 0; p < 2; p++) {
            int e = p * 256 + tid;
            int kr = e >> 4, c4 = e & 15;
            *(float4*)&Bs[kr][c4 * 4] =
                *(const float4*)(W + (size_t)(k0 + kr) * NDIM + n0 + c4 * 4);
        }
        __syncthreads();

#pragma unroll
        for (int kk = 0; kk < 32; kk++) {
            unsigned long long a2[4];
#pragma unroll
            for (int i = 0; i < 4; i++)
                a2[i] = *(const unsigned long long*)&As[kk][ty * 8 + 2 * i];
            float4 bv = *(const float4*)&Bs[kk][tx * 4];
            unsigned long long b2[4] = {pk2(bv.x), pk2(bv.y), pk2(bv.z), pk2(bv.w)};
#pragma unroll
            for (int i = 0; i < 4; i++)
#pragma unroll
                for (int j = 0; j < 4; j++) ffma2(acc[i][j], a2[i], b2[j]);
        }
        __syncthreads();
    }

    // epilogue: bias + exact gelu + HAT gate (+ residual x for MODE 2)
#pragma unroll
    for (int j = 0; j < 4; j++) {
        int n = n0 + tx * 4 + j;
        float bj = bias[n], gj = gate[n];
#pragma unroll
        for (int i = 0; i < 4; i++) {
            float lo, hi;
            unpk2(acc[i][j], lo, hi);
            int r0 = m0 + ty * 8 + 2 * i;
            float v0 = gelu_exact(lo + bj) * gj;
            float v1 = gelu_exact(hi + bj) * gj;
            if (MODE == 2) {
                v0 += xin[(size_t)r0 * NDIM + n];
                v1 += xin[(size_t)(r0 + 1) * NDIM + n];
            }
            C[(size_t)r0 * NDIM + n] = v0;
            C[(size_t)(r0 + 1) * NDIM + n] = v1;
        }
    }
}

// ---------------------------------------------------------------------------
// Launch. Input order: x, t, s, fc1_w, fc1_b, fc2_w, fc2_b, efc1, efc2,
//                      sem_w, sem_b, route_w, larger_w, larger_b, elarger
// ---------------------------------------------------------------------------
extern "C" void kernel_launch(void* const* d_in, const int* in_sizes, int n_in,
                              void* d_out, int out_size) {
    const float* x       = (const float*)d_in[0];
    const int*   tptr    = (const int*)d_in[1];
    const int*   sptr    = (const int*)d_in[2];
    const float* fc1w    = (const float*)d_in[3];
    const float* fc1b    = (const float*)d_in[4];
    const float* fc2w    = (const float*)d_in[5];
    const float* fc2b    = (const float*)d_in[6];
    const float* efc1    = (const float*)d_in[7];
    const float* efc2    = (const float*)d_in[8];
    const float* semw    = (const float*)d_in[9];
    const float* semb    = (const float*)d_in[10];
    const float* routew  = (const float*)d_in[11];
    const float* largerw = (const float*)d_in[12];
    const float* largerb = (const float*)d_in[13];
    const float* elarger = (const float*)d_in[14];
    float* out = (float*)d_out;

    k0_gates<<<1, 768>>>(efc1, efc2, elarger, tptr, sptr);
    k1_sem<<<MROWS / 128, 128>>>(x, semw, semb);
    k2_route<<<MROWS / 256, 256>>>(routew, tptr);
    k3_h2<<<MROWS, 256>>>(x, largerw, largerb);
    gemm_fused<HDIM, ADIM, 1><<<dim3(ADIM / 64, MROWS / 128), 256>>>(fc1w, fc1b, nullptr, nullptr);
    gemm_fused<ADIM, HDIM, 2><<<dim3(HDIM / 64, MROWS / 128), 256>>>(fc2w, fc2b, x, out);
}

// round 3
// speedup vs baseline: 2.3574x; 2.3574x over previous
#include <cuda_runtime.h>
#include <math.h>
#include <stdint.h>

// ---------------------------------------------------------------------------
// BertAdapterCapsuleMask fused pipeline.
// Round 3: tensor-core adapter GEMMs (mma.sync tf32), BK=16 double-buffered
// cp.async, smem < 48KB (no cudaFuncSetAttribute, no static guards).
// Shapes: B=256 S=128 H=768 A=512 N=10 C=3 K=3.  M = 32768.
// ---------------------------------------------------------------------------

#define MROWS 32768
#define HDIM  768
#define ADIM  512
#define NTASK 10
#define CCAP  3
#define KCAP  3

// Scratch (static device globals; no allocations anywhere)
__device__ float g_sem[(size_t)MROWS * 30];
__device__ float g_vote[(size_t)KCAP * MROWS * CCAP];
__device__ float g_h2[(size_t)MROWS * HDIM];
__device__ float g_a[(size_t)MROWS * ADIM];
__device__ float g_gfc1[ADIM];
__device__ float g_gfc2[HDIM];
__device__ float g_glarger[HDIM];

// ---- packed fp32x2 helpers (used by k1 skinny GEMM)
__device__ __forceinline__ unsigned long long pk2(float x) {
    unsigned long long r;
    asm("mov.b64 %0, {%1, %1};" : "=l"(r) : "f"(x));
    return r;
}
__device__ __forceinline__ void ffma2(unsigned long long& d, unsigned long long a,
                                      unsigned long long b) {
    asm("fma.rn.f32x2 %0, %1, %2, %0;" : "+l"(d) : "l"(a), "l"(b));
}
__device__ __forceinline__ void unpk2(unsigned long long v, float& lo, float& hi) {
    asm("mov.b64 {%0, %1}, %2;" : "=f"(lo), "=f"(hi) : "l"(v));
}

__device__ __forceinline__ float gelu_exact(float v) {
    return 0.5f * v * (1.0f + erff(v * 0.7071067811865476f));
}
__device__ __forceinline__ float sigmoid_(float z) {
    return 1.0f / (1.0f + expf(-z));
}

// ---- cp.async helpers
__device__ __forceinline__ void cp_async16(uint32_t smem_dst, const void* gsrc) {
    asm volatile("cp.async.cg.shared.global [%0], [%1], 16;" ::"r"(smem_dst), "l"(gsrc));
}
__device__ __forceinline__ void cp_commit() {
    asm volatile("cp.async.commit_group;");
}
template <int N>
__device__ __forceinline__ void cp_wait() {
    asm volatile("cp.async.wait_group %0;" ::"n"(N));
}

// ---- tf32 mma  (m16n8k8, row.col)
__device__ __forceinline__ void mma_tf32(float4& d, const uint32_t* a, const uint32_t* b) {
    asm volatile(
        "mma.sync.aligned.m16n8k8.row.col.f32.tf32.tf32.f32 "
        "{%0,%1,%2,%3}, {%4,%5,%6,%7}, {%8,%9}, {%0,%1,%2,%3};"
        : "+f"(d.x), "+f"(d.y), "+f"(d.z), "+f"(d.w)
        : "r"(a[0]), "r"(a[1]), "r"(a[2]), "r"(a[3]), "r"(b[0]), "r"(b[1]));
}

// ---------------------------------------------------------------------------
// K0: HAT gates.  g = sigmoid(s * e[t])
// ---------------------------------------------------------------------------
__global__ void k0_gates(const float* __restrict__ efc1, const float* __restrict__ efc2,
                         const float* __restrict__ elarger,
                         const int* __restrict__ tp, const int* __restrict__ sp) {
    int t = *tp;
    float s = (float)(*sp);
    int h = threadIdx.x;  // 768 threads
    g_glarger[h] = sigmoid_(s * elarger[t * HDIM + h]);
    g_gfc2[h]    = sigmoid_(s * efc2[t * HDIM + h]);
    if (h < ADIM) g_gfc1[h] = sigmoid_(s * efc1[t * ADIM + h]);
}

// ---------------------------------------------------------------------------
// K1: semantic-capsule skinny GEMM (f32x2 SIMT) — measured-passing, unchanged.
// ---------------------------------------------------------------------------
__global__ __launch_bounds__(128) void k1_sem(const float* __restrict__ x,
                                              const float* __restrict__ semw,
                                              const float* __restrict__ semb) {
    __shared__ float Xs[128][65];
    __shared__ float Ws[64][32];
    __shared__ float bs[32];

    int tid = threadIdx.x;
    int m0 = blockIdx.x * 128;

    if (tid < 30) {
        int c = tid / 10, n = tid % 10;
        bs[tid] = semb[n * 3 + c];
    }

    unsigned long long acc[15];
#pragma unroll
    for (int j = 0; j < 15; j++) acc[j] = 0ull;

    for (int k0 = 0; k0 < HDIM; k0 += 64) {
#pragma unroll
        for (int p = 0; p < 16; p++) {
            int e = p * 128 + tid;
            int r = e >> 4, c4 = e & 15;
            float4 v = *(const float4*)(x + (size_t)(m0 + r) * HDIM + k0 + c4 * 4);
            Xs[r][c4 * 4 + 0] = v.x;
            Xs[r][c4 * 4 + 1] = v.y;
            Xs[r][c4 * 4 + 2] = v.z;
            Xs[r][c4 * 4 + 3] = v.w;
        }
#pragma unroll
        for (int p = 0; p < 15; p++) {
            int e = p * 128 + tid;
            int kk = e / 30, o = e % 30;
            int c = o / 10, n = o % 10;
            Ws[kk][o] = semw[n * HDIM * 3 + (k0 + kk) * 3 + c];
        }
        __syncthreads();

#pragma unroll 4
        for (int kk = 0; kk < 64; kk++) {
            unsigned long long x2 = pk2(Xs[tid][kk]);
#pragma unroll
            for (int j = 0; j < 15; j++) {
                unsigned long long w2 = *(const unsigned long long*)&Ws[kk][2 * j];
                ffma2(acc[j], x2, w2);
            }
        }
        __syncthreads();
    }

    int m = m0 + tid;
#pragma unroll
    for (int j = 0; j < 15; j++) {
        float lo, hi;
        unpk2(acc[j], lo, hi);
        g_sem[(size_t)m * 30 + 2 * j]     = lo + bs[2 * j];
        g_sem[(size_t)m * 30 + 2 * j + 1] = hi + bs[2 * j + 1];
    }
}

// ---------------------------------------------------------------------------
// K2: squash + dynamic routing — measured-passing, unchanged.
// ---------------------------------------------------------------------------
__global__ __launch_bounds__(256) void k2_route(const float* __restrict__ routew,
                                                const int* __restrict__ tp) {
    __shared__ float rw[KCAP * NTASK * CCAP * CCAP];
    int tid = threadIdx.x;
    if (tid < 270) rw[tid] = routew[tid];
    __syncthreads();

    int t = *tp;
    int m = blockIdx.x * 256 + tid;

    float v[30];
    const float* srow = &g_sem[(size_t)m * 30];
#pragma unroll
    for (int i = 0; i < 30; i++) v[i] = srow[i];

#pragma unroll
    for (int c = 0; c < 3; c++) {
        float sn = 1e-16f;
#pragma unroll
        for (int n = 0; n < 10; n++) { float q = v[c * 10 + n]; sn += q * q; }
        float sc = sqrtf(sn) / (1.0f + sn);
#pragma unroll
        for (int n = 0; n < 10; n++) v[c * 10 + n] *= sc;
    }

#pragma unroll
    for (int k = 0; k < 3; k++) {
        float pr[10][3];
#pragma unroll
        for (int n = 0; n < 10; n++) {
            float u0 = v[n * 3 + 0], u1 = v[n * 3 + 1], u2 = v[n * 3 + 2];
#pragma unroll
            for (int d = 0; d < 3; d++) {
                int b = ((k * 10 + n) * 3) * 3 + d;
                pr[n][d] = u0 * rw[b] + u1 * rw[b + 3] + u2 * rw[b + 6];
            }
        }
        float lg[10];
#pragma unroll
        for (int n = 0; n < 10; n++) lg[n] = 0.0f;

        float vote0 = 0.f, vote1 = 0.f, vote2 = 0.f;
#pragma unroll
        for (int it = 0; it < 3; it++) {
            float mx = -3.4e38f;
#pragma unroll
            for (int n = 0; n < 10; n++) {
                lg[n] = (n <= t) ? lg[n] : -10000.0f;
                mx = fmaxf(mx, lg[n]);
            }
            float e[10], ssum = 0.f;
#pragma unroll
            for (int n = 0; n < 10; n++) { e[n] = expf(lg[n] - mx); ssum += e[n]; }
            float inv = 1.0f / ssum;
            vote0 = vote1 = vote2 = 0.f;
#pragma unroll
            for (int n = 0; n < 10; n++) {
                float p = e[n] * inv;
                vote0 += p * pr[n][0];
                vote1 += p * pr[n][1];
                vote2 += p * pr[n][2];
            }
            if (it < 2) {
                float sn = vote0 * vote0 + vote1 * vote1 + vote2 * vote2 + 1e-16f;
                float sc = sqrtf(sn) / (1.0f + sn);
                float o0 = vote0 * sc, o1 = vote1 * sc, o2 = vote2 * sc;
#pragma unroll
                for (int n = 0; n < 10; n++)
                    lg[n] += pr[n][0] * o0 + pr[n][1] * o1 + pr[n][2] * o2;
            }
        }
        size_t base = ((size_t)k * MROWS + m) * 3;
        g_vote[base + 0] = vote0;
        g_vote[base + 1] = vote1;
        g_vote[base + 2] = vote2;
    }
}

// ---------------------------------------------------------------------------
// K3: h2 = x + glarger * (vote9 @ larger_w + larger_b) — unchanged.
// ---------------------------------------------------------------------------
__global__ __launch_bounds__(256) void k3_h2(const float* __restrict__ x,
                                             const float* __restrict__ lw,
                                             const float* __restrict__ lb) {
    __shared__ float v9[9];
    int m = blockIdx.x;
    int tid = threadIdx.x;
    if (tid < 9) v9[tid] = g_vote[(size_t)m * 9 + tid];
    __syncthreads();
#pragma unroll
    for (int p = 0; p < 3; p++) {
        int h = tid + p * 256;
        float acc = lb[h];
#pragma unroll
        for (int j = 0; j < 9; j++) acc += v9[j] * lw[j * HDIM + h];
        g_h2[(size_t)m * HDIM + h] = x[(size_t)m * HDIM + h] + g_glarger[h] * acc;
    }
}

// ---------------------------------------------------------------------------
// Adapter GEMMs on tensor cores: mma.sync m16n8k8 tf32 (single pass).
// BM=128 BN=128 BK=16, 256 threads = 8 warps (2 along M x 4 along N),
// warp tile 64x32 -> 4x4 mma tiles, 64 fp32 accumulators per thread.
// 2-stage cp.async double buffering; total smem 37.9 KB (< 48 KB opt-in limit).
// MODE 1: a   = gelu(h2 @ fc1_w + b) * gfc1
// MODE 2: out = x + gelu(a @ fc2_w + b) * gfc2
// ---------------------------------------------------------------------------
#define ASTRIDE 20               // 16 + 4 pad: A-frag banks (20*g+tg)%32 all distinct
#define BSTRIDE 136              // 128 + 8 pad: B-frag banks (8*tg+g) all distinct
#define ASIZE (128 * ASTRIDE)    // 2560 floats per A stage
#define BSIZE (16 * BSTRIDE)     // 2176 floats per B stage
#define GEMM_SMEM_BYTES ((2 * ASIZE + 2 * BSIZE) * 4)   // 37888 B

template <int KDIM, int NDIM, int MODE>
__global__ __launch_bounds__(256, 2) void gemm_mma(const float* __restrict__ W,
                                                   const float* __restrict__ bias,
                                                   const float* __restrict__ xin,
                                                   float* __restrict__ outp) {
    extern __shared__ float smem[];
    float* AsBase = smem;               // [2][128][ASTRIDE]
    float* BsBase = smem + 2 * ASIZE;   // [2][16][BSTRIDE]

    const float* A    = (MODE == 1) ? g_h2 : g_a;
    const float* gate = (MODE == 1) ? g_gfc1 : g_gfc2;
    float* C          = (MODE == 1) ? g_a : outp;

    const int tid = threadIdx.x;
    const int lane = tid & 31;
    const int wid = tid >> 5;
    const int warp_m = wid >> 2;   // 0..1
    const int warp_n = wid & 3;    // 0..3
    const int g = lane >> 2;       // 0..7
    const int tg = lane & 3;       // 0..3

    const int n0 = blockIdx.x * 128;
    const int m0 = blockIdx.y * 128;

    // staging indices: A tile 128x16 = 512 float4 (2 per thread),
    //                  B tile 16x128 = 512 float4 (2 per thread)
    const int ar = tid >> 2;        // 0..63 ; +64 on second step
    const int akq = tid & 3;        // float4 column within 16-wide k
    const int bkr = tid >> 5;       // 0..7  ; +8 on second step
    const int bnq = tid & 31;       // float4 column within 128-wide n

    uint32_t sA = (uint32_t)__cvta_generic_to_shared(AsBase);
    uint32_t sB = (uint32_t)__cvta_generic_to_shared(BsBase);

    float4 acc[4][4];
#pragma unroll
    for (int i = 0; i < 4; i++)
#pragma unroll
        for (int j = 0; j < 4; j++) acc[i][j] = make_float4(0.f, 0.f, 0.f, 0.f);

    const int KT = KDIM / 16;

    auto prefetch = [&](int kt, int buf) {
        const float* Ag = A + (size_t)m0 * KDIM + kt * 16;
        const float* Bg = W + (size_t)kt * 16 * NDIM + n0;
        uint32_t abase = sA + (uint32_t)(buf * ASIZE) * 4;
        uint32_t bbase = sB + (uint32_t)(buf * BSIZE) * 4;
#pragma unroll
        for (int p = 0; p < 2; p++) {
            int r = ar + p * 64;
            cp_async16(abase + (uint32_t)(r * ASTRIDE + akq * 4) * 4,
                       Ag + (size_t)r * KDIM + akq * 4);
        }
#pragma unroll
        for (int p = 0; p < 2; p++) {
            int kr = bkr + p * 8;
            cp_async16(bbase + (uint32_t)(kr * BSTRIDE + bnq * 4) * 4,
                       Bg + (size_t)kr * NDIM + bnq * 4);
        }
        cp_commit();
    };

    prefetch(0, 0);

    for (int kt = 0; kt < KT; kt++) {
        int buf = kt & 1;
        if (kt + 1 < KT) {
            prefetch(kt + 1, buf ^ 1);
            cp_wait<1>();
        } else {
            cp_wait<0>();
        }
        __syncthreads();

        const float* Ab = AsBase + buf * ASIZE;
        const float* Bb = BsBase + buf * BSIZE;

#pragma unroll
        for (int ks = 0; ks < 2; ks++) {
            const int kb = ks * 8;
            uint32_t afr[4][4];
#pragma unroll
            for (int i = 0; i < 4; i++) {
                int row = warp_m * 64 + i * 16 + g;
                afr[i][0] = __float_as_uint(Ab[row * ASTRIDE + kb + tg]);
                afr[i][1] = __float_as_uint(Ab[(row + 8) * ASTRIDE + kb + tg]);
                afr[i][2] = __float_as_uint(Ab[row * ASTRIDE + kb + tg + 4]);
                afr[i][3] = __float_as_uint(Ab[(row + 8) * ASTRIDE + kb + tg + 4]);
            }
            uint32_t bfr[4][2];
#pragma unroll
            for (int j = 0; j < 4; j++) {
                int n = warp_n * 32 + j * 8 + g;
                bfr[j][0] = __float_as_uint(Bb[(kb + tg) * BSTRIDE + n]);
                bfr[j][1] = __float_as_uint(Bb[(kb + tg + 4) * BSTRIDE + n]);
            }
#pragma unroll
            for (int i = 0; i < 4; i++)
#pragma unroll
                for (int j = 0; j < 4; j++) mma_tf32(acc[i][j], afr[i], bfr[j]);
        }
        __syncthreads();
    }

    // epilogue: bias + exact gelu + HAT gate (+ residual for MODE 2)
#pragma unroll
    for (int j = 0; j < 4; j++) {
        int col = n0 + warp_n * 32 + j * 8 + 2 * tg;
        float2 bb = *(const float2*)&bias[col];
        float2 gg = *(const float2*)&gate[col];
#pragma unroll
        for (int i = 0; i < 4; i++) {
            int row = m0 + warp_m * 64 + i * 16 + g;
            float v00 = gelu_exact(acc[i][j].x + bb.x) * gg.x;
            float v01 = gelu_exact(acc[i][j].y + bb.y) * gg.y;
            float v10 = gelu_exact(acc[i][j].z + bb.x) * gg.x;
            float v11 = gelu_exact(acc[i][j].w + bb.y) * gg.y;
            if (MODE == 2) {
                float2 x0 = *(const float2*)&xin[(size_t)row * NDIM + col];
                float2 x1 = *(const float2*)&xin[(size_t)(row + 8) * NDIM + col];
                v00 += x0.x; v01 += x0.y;
                v10 += x1.x; v11 += x1.y;
            }
            *(float2*)&C[(size_t)row * NDIM + col] = make_float2(v00, v01);
            *(float2*)&C[(size_t)(row + 8) * NDIM + col] = make_float2(v10, v11);
        }
    }
}

// ---------------------------------------------------------------------------
// Launch. Input order: x, t, s, fc1_w, fc1_b, fc2_w, fc2_b, efc1, efc2,
//                      sem_w, sem_b, route_w, larger_w, larger_b, elarger
// ---------------------------------------------------------------------------
extern "C" void kernel_launch(void* const* d_in, const int* in_sizes, int n_in,
                              void* d_out, int out_size) {
    const float* x       = (const float*)d_in[0];
    const int*   tptr    = (const int*)d_in[1];
    const int*   sptr    = (const int*)d_in[2];
    const float* fc1w    = (const float*)d_in[3];
    const float* fc1b    = (const float*)d_in[4];
    const float* fc2w    = (const float*)d_in[5];
    const float* fc2b    = (const float*)d_in[6];
    const float* efc1    = (const float*)d_in[7];
    const float* efc2    = (const float*)d_in[8];
    const float* semw    = (const float*)d_in[9];
    const float* semb    = (const float*)d_in[10];
    const float* routew  = (const float*)d_in[11];
    const float* largerw = (const float*)d_in[12];
    const float* largerb = (const float*)d_in[13];
    const float* elarger = (const float*)d_in[14];
    float* out = (float*)d_out;

    k0_gates<<<1, 768>>>(efc1, efc2, elarger, tptr, sptr);
    k1_sem<<<MROWS / 128, 128>>>(x, semw, semb);
    k2_route<<<MROWS / 256, 256>>>(routew, tptr);
    k3_h2<<<MROWS, 256>>>(x, largerw, largerb);
    gemm_mma<HDIM, ADIM, 1><<<dim3(ADIM / 128, MROWS / 128), 256, GEMM_SMEM_BYTES>>>(
        fc1w, fc1b, nullptr, nullptr);
    gemm_mma<ADIM, HDIM, 2><<<dim3(HDIM / 128, MROWS / 128), 256, GEMM_SMEM_BYTES>>>(
        fc2w, fc2b, x, out);
}